// round 12
// baseline (speedup 1.0000x reference)
#include <cuda_runtime.h>
#include <cuda_fp16.h>
#include <cstdint>
#include <cfloat>

#define N_ROWS 32768
#define DIM    512
#define K_CODES 8192

#define BM 128
#define BN 256
#define KC 64                    // 64 fp16 = 128B rows
#define NVC (DIM / KC)           // 8 chunks (hh only)
#define A_TILE_BYTES 16384       // 128 rows x 128B
#define B_TILE_BYTES 32768       // 256 rows x 128B
#define STAGE_BYTES (A_TILE_BYTES + B_TILE_BYTES)   // 48KB
#define NSTAGE 3
#define SMEM_TOTAL (NSTAGE * STAGE_BYTES)           // 144KB
#define CAP 256                  // candidate slots per row

// statistical margin: err std sigma_d ~= 1.21e-5 * ||x||_2 ; margin ~= 20 sigma
#define MARGIN_A 2.5e-4f
#define MARGIN_B 3.0e-4f

// ---- scratch ----
__device__ unsigned long long g_best[N_ROWS];
__device__ unsigned int  g_candcnt[N_ROWS];
__device__ float         g_margin[N_ROWS];
__device__ unsigned int  g_cand[(size_t)N_ROWS * CAP];   // columns only (32MB)
__device__ float g_cnorm_arr[K_CODES];
__device__ __half g_Xh[(size_t)N_ROWS * DIM];
__device__ __half g_Ch[(size_t)K_CODES * DIM];

// ---- helpers ----
__device__ __forceinline__ uint32_t smem_u32(const void* p) {
    uint32_t a;
    asm("{ .reg .u64 t; cvta.to.shared.u64 t, %1; cvt.u32.u64 %0, t; }" : "=r"(a) : "l"(p));
    return a;
}
#define CP_ASYNC16(dst, src) \
    asm volatile("cp.async.cg.shared.global [%0], [%1], 16;" :: "r"(dst), "l"(src) : "memory")
#define CP_COMMIT() asm volatile("cp.async.commit_group;" ::: "memory")

__device__ __forceinline__ void ldmatrix_x4(uint32_t* r, uint32_t addr) {
    asm volatile("ldmatrix.sync.aligned.m8n8.x4.shared.b16 {%0,%1,%2,%3}, [%4];"
                 : "=r"(r[0]), "=r"(r[1]), "=r"(r[2]), "=r"(r[3]) : "r"(addr));
}
__device__ __forceinline__ void mma_16816(float* d, const uint32_t* a, uint32_t b0, uint32_t b1) {
    asm volatile(
        "mma.sync.aligned.m16n8k16.row.col.f32.f16.f16.f32 "
        "{%0,%1,%2,%3}, {%4,%5,%6,%7}, {%8,%9}, {%0,%1,%2,%3};"
        : "+f"(d[0]), "+f"(d[1]), "+f"(d[2]), "+f"(d[3])
        : "r"(a[0]), "r"(a[1]), "r"(a[2]), "r"(a[3]), "r"(b0), "r"(b1));
}
__device__ __forceinline__ uint32_t sw128(uint32_t off) { return off ^ ((off >> 3) & 0x70); }
__device__ __forceinline__ unsigned float_to_ordered(float f) {
    unsigned u = __float_as_uint(f);
    return u ^ (unsigned)(((int)u >> 31) | 0x80000000);
}
__device__ __forceinline__ float ordered_to_float(unsigned u) {
    unsigned v = (u & 0x80000000u) ? (u ^ 0x80000000u) : ~u;
    return __uint_as_float(v);
}

// ================== fused prep: split + norms + reset ======================
// one warp per X row: write fp16 halves, compute ||x||_2, reset state
__global__ void prep_x_kernel(const float* __restrict__ X) {
    int warp = (blockIdx.x * blockDim.x + threadIdx.x) >> 5;
    int lane = threadIdx.x & 31;
    if (warp >= N_ROWS) return;
    const float4* row = (const float4*)(X + (size_t)warp * DIM);
    __half2* dst = (__half2*)(g_Xh + (size_t)warp * DIM);
    float s = 0.f;
    #pragma unroll
    for (int t = 0; t < 4; t++) {
        int i4 = lane + 32 * t;
        float4 v = row[i4];
        s += v.x * v.x + v.y * v.y + v.z * v.z + v.w * v.w;
        dst[i4 * 2 + 0] = __half2(__float2half_rn(v.x), __float2half_rn(v.y));
        dst[i4 * 2 + 1] = __half2(__float2half_rn(v.z), __float2half_rn(v.w));
    }
    #pragma unroll
    for (int o = 16; o > 0; o >>= 1) s += __shfl_down_sync(0xffffffffu, s, o);
    if (lane == 0) {
        g_margin[warp]  = MARGIN_A * sqrtf(s) + MARGIN_B;
        g_best[warp]    = 0xFFFFFFFFFFFFFFFFull;
        g_candcnt[warp] = 0u;
    }
}
// one warp per codebook row: write fp16 halves + ||c||^2
__global__ void prep_c_kernel(const float* __restrict__ C) {
    int warp = (blockIdx.x * blockDim.x + threadIdx.x) >> 5;
    int lane = threadIdx.x & 31;
    if (warp >= K_CODES) return;
    const float4* row = (const float4*)(C + (size_t)warp * DIM);
    __half2* dst = (__half2*)(g_Ch + (size_t)warp * DIM);
    float s = 0.f;
    #pragma unroll
    for (int t = 0; t < 4; t++) {
        int i4 = lane + 32 * t;
        float4 v = row[i4];
        s += v.x * v.x + v.y * v.y + v.z * v.z + v.w * v.w;
        dst[i4 * 2 + 0] = __half2(__float2half_rn(v.x), __float2half_rn(v.y));
        dst[i4 * 2 + 1] = __half2(__float2half_rn(v.z), __float2half_rn(v.w));
    }
    #pragma unroll
    for (int o = 16; o > 0; o >>= 1) s += __shfl_down_sync(0xffffffffu, s, o);
    if (lane == 0) g_cnorm_arr[warp] = s;
}

// ================== pass 1: hh GEMM + argmin + candidate dump ==============
__device__ __forceinline__ void issue_loads(int vc, int stage, uint32_t smbase,
                                            int row0, int col0, int tid) {
    const int kof = vc * KC;
    const uint32_t sa = smbase + stage * STAGE_BYTES;
    const uint32_t sb = sa + A_TILE_BYTES;
    #pragma unroll
    for (int j = 0; j < 4; j++) {         // A: 1024 segs
        int o = tid + j * 256, r = o >> 3, seg = o & 7;
        uint32_t sw = sw128((uint32_t)(r * 128 + seg * 16));
        CP_ASYNC16(sa + sw, g_Xh + (size_t)(row0 + r) * DIM + kof + seg * 8);
    }
    #pragma unroll
    for (int j = 0; j < 8; j++) {         // B: 2048 segs
        int o = tid + j * 256, r = o >> 3, seg = o & 7;
        uint32_t sw = sw128((uint32_t)(r * 128 + seg * 16));
        CP_ASYNC16(sb + sw, g_Ch + (size_t)(col0 + r) * DIM + kof + seg * 8);
    }
}

__global__ void __launch_bounds__(256, 1)
gemm_argmin_mma(void) {
    extern __shared__ char smem[];
    const uint32_t smbase = smem_u32(smem);
    const int tid  = threadIdx.x;
    const int wid  = tid >> 5;
    const int lane = tid & 31;
    const int warp_m = wid >> 2;      // 0..1, 64 rows
    const int warp_n = wid & 3;       // 0..3, 64 cols
    const int row0 = blockIdx.y * BM;
    const int col0 = blockIdx.x * BN;

    float acc[4][8][4];               // 64x64 warp tile
    #pragma unroll
    for (int a = 0; a < 4; a++)
        #pragma unroll
        for (int b = 0; b < 8; b++)
            #pragma unroll
            for (int c = 0; c < 4; c++) acc[a][b][c] = 0.f;

    const int a_row = warp_m * 64 + (lane & 7) + 8 * ((lane >> 3) & 1);
    const int a_cb0 = (lane >> 4) * 16;
    const int b_row = warp_n * 64 + (lane & 7) + 8 * (lane >> 4);
    const int b_cb0 = ((lane >> 3) & 1) * 16;

    issue_loads(0, 0, smbase, row0, col0, tid);
    CP_COMMIT();
    issue_loads(1, 1, smbase, row0, col0, tid);
    CP_COMMIT();

    #pragma unroll 1
    for (int vc = 0; vc < NVC; vc++) {
        if (vc < NVC - 1) asm volatile("cp.async.wait_group 1;" ::: "memory");
        else              asm volatile("cp.async.wait_group 0;" ::: "memory");
        __syncthreads();
        if (vc + 2 < NVC) {
            issue_loads(vc + 2, (vc + 2) % NSTAGE, smbase, row0, col0, tid);
            CP_COMMIT();
        }
        const uint32_t sa = smbase + (vc % NSTAGE) * STAGE_BYTES;
        const uint32_t sb = sa + A_TILE_BYTES;
        #pragma unroll
        for (int ks = 0; ks < KC / 16; ks++) {
            uint32_t afr[4][4], bfr[4][4];
            #pragma unroll
            for (int mi = 0; mi < 4; mi++) {
                uint32_t off = (uint32_t)((a_row + mi * 16) * 128 + ks * 32 + a_cb0);
                ldmatrix_x4(afr[mi], sa + sw128(off));
            }
            #pragma unroll
            for (int nj = 0; nj < 4; nj++) {
                uint32_t off = (uint32_t)((b_row + nj * 16) * 128 + ks * 32 + b_cb0);
                ldmatrix_x4(bfr[nj], sb + sw128(off));
            }
            #pragma unroll
            for (int mi = 0; mi < 4; mi++)
                #pragma unroll
                for (int ni = 0; ni < 8; ni++) {
                    const uint32_t* bf = bfr[ni >> 1];
                    uint32_t b0 = (ni & 1) ? bf[2] : bf[0];
                    uint32_t b1 = (ni & 1) ? bf[3] : bf[1];
                    mma_16816(acc[mi][ni], afr[mi], b0, b1);
                }
        }
        // stage (vc+2)%3 written next iter was last read at vc-1; the barrier
        // at the top of iteration vc+1 orders the reuse.
    }

    // ---- epilogue: approx argmin + live-threshold candidate dump ----
    float cn[8][2];
    #pragma unroll
    for (int ni = 0; ni < 8; ni++) {
        int col = col0 + warp_n * 64 + ni * 8 + (lane & 3) * 2;
        cn[ni][0] = __ldg(&g_cnorm_arr[col]);
        cn[ni][1] = __ldg(&g_cnorm_arr[col + 1]);
    }
    #pragma unroll
    for (int mi = 0; mi < 4; mi++) {
        #pragma unroll
        for (int rp = 0; rp < 2; rp++) {
            const int row = row0 + warp_m * 64 + mi * 16 + (lane >> 2) + 8 * rp;
            float best_d = FLT_MAX;
            int   best_c = 0;
            #pragma unroll
            for (int ni = 0; ni < 8; ni++)
                #pragma unroll
                for (int c = 0; c < 2; c++) {
                    int col = col0 + warp_n * 64 + ni * 8 + (lane & 3) * 2 + c;
                    float d = cn[ni][c] - 2.0f * acc[mi][ni][rp * 2 + c];
                    if (d < best_d) { best_d = d; best_c = col; }
                }
            unsigned long long p =
                ((unsigned long long)float_to_ordered(best_d) << 32) | (unsigned)best_c;
            float qd = best_d;
            #pragma unroll
            for (int m = 1; m < 4; m <<= 1) {
                unsigned long long q = __shfl_xor_sync(0xffffffffu, p, m);
                if (q < p) p = q;
                qd = fminf(qd, __shfl_xor_sync(0xffffffffu, qd, m));
            }
            if ((lane & 3) == 0) atomicMin(&g_best[row], p);
            unsigned long long gb = *((volatile unsigned long long*)&g_best[row]);
            float gl = ordered_to_float((unsigned)(gb >> 32));
            const float thr = fminf(qd, gl) + __ldg(&g_margin[row]);
            #pragma unroll
            for (int ni = 0; ni < 8; ni++)
                #pragma unroll
                for (int c = 0; c < 2; c++) {
                    int col = col0 + warp_n * 64 + ni * 8 + (lane & 3) * 2 + c;
                    float d = cn[ni][c] - 2.0f * acc[mi][ni][rp * 2 + c];
                    if (d <= thr) {
                        unsigned slot = atomicAdd(&g_candcnt[row], 1u);
                        if (slot < CAP)
                            g_cand[(size_t)row * CAP + slot] = (unsigned)col;
                    }
                }
        }
    }
}

// ========== pass 2: exact fp64 refinement + fused gather ===================
__device__ __forceinline__ double warp_exact_dist(const float* __restrict__ X,
                                                  const float* __restrict__ C,
                                                  int row, int col, int lane) {
    const float* xr = X + (size_t)row * DIM;
    const float* cr = C + (size_t)col * DIM;
    double dot = 0.0, cn = 0.0;
    for (int j = lane; j < DIM; j += 32) {
        double cv = (double)cr[j];
        dot += (double)xr[j] * cv;
        cn  += cv * cv;
    }
    #pragma unroll
    for (int o = 16; o > 0; o >>= 1) {
        dot += __shfl_down_sync(0xffffffffu, dot, o);
        cn  += __shfl_down_sync(0xffffffffu, cn,  o);
    }
    return cn - 2.0 * dot;   // valid on lane 0
}

__global__ void refine_gather_kernel(const float* __restrict__ X,
                                     const float* __restrict__ C,
                                     float* __restrict__ out) {
    const int warp = (blockIdx.x * blockDim.x + threadIdx.x) >> 5;
    const int lane = threadIdx.x & 31;
    if (warp >= N_ROWS) return;
    const int row = warp;

    const unsigned cnt_raw = g_candcnt[row];
    double best_d = DBL_MAX;
    int    best_c = 0x7FFFFFFF;

    if (cnt_raw > CAP) {
        for (int col = 0; col < K_CODES; col++) {
            double d = warp_exact_dist(X, C, row, col, lane);
            if (lane == 0 && d < best_d) { best_d = d; best_c = col; }
        }
    } else {
        const int cnt = (int)cnt_raw;
        for (int i = 0; i < cnt; i++) {
            int c = (int)g_cand[(size_t)row * CAP + i];
            double d = warp_exact_dist(X, C, row, c, lane);
            if (lane == 0 && (d < best_d || (d == best_d && c < best_c))) {
                best_d = d; best_c = c;
            }
        }
    }
    best_c = __shfl_sync(0xffffffffu, best_c, 0);

    // fused gather: out0 = q; out1 = x + (q - x) with fp32 rounding
    const float4* src = (const float4*)(C + (size_t)best_c * DIM);
    const float4* xs  = (const float4*)(X + (size_t)row * DIM);
    float4* d0 = (float4*)(out + (size_t)row * DIM);
    float4* d1 = (float4*)(out + ((size_t)N_ROWS + row) * DIM);
    #pragma unroll
    for (int t = 0; t < 4; t++) {
        int i = lane + 32 * t;
        float4 q = src[i];
        float4 x = xs[i];
        d0[i] = q;
        float4 st;
        st.x = x.x + (q.x - x.x);
        st.y = x.y + (q.y - x.y);
        st.z = x.z + (q.z - x.z);
        st.w = x.w + (q.w - x.w);
        d1[i] = st;
    }
}

// ===========================================================================
extern "C" void kernel_launch(void* const* d_in, const int* in_sizes, int n_in,
                              void* d_out, int out_size) {
    const float* x  = (const float*)d_in[0];
    const float* cb = (const float*)d_in[1];
    float* out = (float*)d_out;
    (void)in_sizes; (void)n_in; (void)out_size;

    cudaFuncSetAttribute(gemm_argmin_mma,
                         cudaFuncAttributeMaxDynamicSharedMemorySize, SMEM_TOTAL);

    prep_x_kernel<<<(N_ROWS * 32 + 255) / 256, 256>>>(x);
    prep_c_kernel<<<(K_CODES * 32 + 255) / 256, 256>>>(cb);

    dim3 grid(K_CODES / BN, N_ROWS / BM);   // (32, 256)
    gemm_argmin_mma<<<grid, 256, SMEM_TOTAL>>>();

    refine_gather_kernel<<<(N_ROWS * 32 + 255) / 256, 256>>>(x, cb, out);
}

// round 14
// speedup vs baseline: 1.1537x; 1.1537x over previous
#include <cuda_runtime.h>
#include <cuda_fp16.h>
#include <cstdint>
#include <cfloat>

#define N_ROWS 32768
#define DIM    512
#define K_CODES 8192

#define BM 128
#define BN 128
#define KC 64                    // 64 fp16 = 128B rows
#define NVC (DIM / KC)           // 8 chunks (hh only)
#define TILE_BYTES 16384         // 128 rows x 128B
#define STAGE_BYTES (2 * TILE_BYTES)   // A + B = 32KB
#define NSTAGE 3
#define SMEM_TOTAL (NSTAGE * STAGE_BYTES)   // 96KB -> 2 CTAs/SM
#define CAP 256                  // candidate slots per row

// statistical margin: err std sigma_d ~= 1.21e-5 * ||x||_2 ; margin ~= 20 sigma
#define MARGIN_A 2.5e-4f
#define MARGIN_B 3.0e-4f

// ---- scratch ----
__device__ unsigned long long g_best[N_ROWS];
__device__ unsigned int  g_candcnt[N_ROWS];
__device__ float         g_margin[N_ROWS];
__device__ unsigned int  g_cand[(size_t)N_ROWS * CAP];   // columns only (32MB)
__device__ float g_cnorm_arr[K_CODES];
__device__ __half g_Xh[(size_t)N_ROWS * DIM];
__device__ __half g_Ch[(size_t)K_CODES * DIM];

// ---- helpers ----
__device__ __forceinline__ uint32_t smem_u32(const void* p) {
    uint32_t a;
    asm("{ .reg .u64 t; cvta.to.shared.u64 t, %1; cvt.u32.u64 %0, t; }" : "=r"(a) : "l"(p));
    return a;
}
#define CP_ASYNC16(dst, src) \
    asm volatile("cp.async.cg.shared.global [%0], [%1], 16;" :: "r"(dst), "l"(src) : "memory")
#define CP_COMMIT() asm volatile("cp.async.commit_group;" ::: "memory")

__device__ __forceinline__ void ldmatrix_x4(uint32_t* r, uint32_t addr) {
    asm volatile("ldmatrix.sync.aligned.m8n8.x4.shared.b16 {%0,%1,%2,%3}, [%4];"
                 : "=r"(r[0]), "=r"(r[1]), "=r"(r[2]), "=r"(r[3]) : "r"(addr));
}
__device__ __forceinline__ void mma_16816(float* d, const uint32_t* a, uint32_t b0, uint32_t b1) {
    asm volatile(
        "mma.sync.aligned.m16n8k16.row.col.f32.f16.f16.f32 "
        "{%0,%1,%2,%3}, {%4,%5,%6,%7}, {%8,%9}, {%0,%1,%2,%3};"
        : "+f"(d[0]), "+f"(d[1]), "+f"(d[2]), "+f"(d[3])
        : "r"(a[0]), "r"(a[1]), "r"(a[2]), "r"(a[3]), "r"(b0), "r"(b1));
}
__device__ __forceinline__ uint32_t sw128(uint32_t off) { return off ^ ((off >> 3) & 0x70); }
__device__ __forceinline__ unsigned float_to_ordered(float f) {
    unsigned u = __float_as_uint(f);
    return u ^ (unsigned)(((int)u >> 31) | 0x80000000);
}
__device__ __forceinline__ float ordered_to_float(unsigned u) {
    unsigned v = (u & 0x80000000u) ? (u ^ 0x80000000u) : ~u;
    return __uint_as_float(v);
}

// ================== fused prep: split + norms + reset ======================
__global__ void prep_x_kernel(const float* __restrict__ X) {
    int warp = (blockIdx.x * blockDim.x + threadIdx.x) >> 5;
    int lane = threadIdx.x & 31;
    if (warp >= N_ROWS) return;
    const float4* row = (const float4*)(X + (size_t)warp * DIM);
    __half2* dst = (__half2*)(g_Xh + (size_t)warp * DIM);
    float s = 0.f;
    #pragma unroll
    for (int t = 0; t < 4; t++) {
        int i4 = lane + 32 * t;
        float4 v = row[i4];
        s += v.x * v.x + v.y * v.y + v.z * v.z + v.w * v.w;
        dst[i4 * 2 + 0] = __half2(__float2half_rn(v.x), __float2half_rn(v.y));
        dst[i4 * 2 + 1] = __half2(__float2half_rn(v.z), __float2half_rn(v.w));
    }
    #pragma unroll
    for (int o = 16; o > 0; o >>= 1) s += __shfl_down_sync(0xffffffffu, s, o);
    if (lane == 0) {
        g_margin[warp]  = MARGIN_A * sqrtf(s) + MARGIN_B;
        g_best[warp]    = 0xFFFFFFFFFFFFFFFFull;
        g_candcnt[warp] = 0u;
    }
}
__global__ void prep_c_kernel(const float* __restrict__ C) {
    int warp = (blockIdx.x * blockDim.x + threadIdx.x) >> 5;
    int lane = threadIdx.x & 31;
    if (warp >= K_CODES) return;
    const float4* row = (const float4*)(C + (size_t)warp * DIM);
    __half2* dst = (__half2*)(g_Ch + (size_t)warp * DIM);
    float s = 0.f;
    #pragma unroll
    for (int t = 0; t < 4; t++) {
        int i4 = lane + 32 * t;
        float4 v = row[i4];
        s += v.x * v.x + v.y * v.y + v.z * v.z + v.w * v.w;
        dst[i4 * 2 + 0] = __half2(__float2half_rn(v.x), __float2half_rn(v.y));
        dst[i4 * 2 + 1] = __half2(__float2half_rn(v.z), __float2half_rn(v.w));
    }
    #pragma unroll
    for (int o = 16; o > 0; o >>= 1) s += __shfl_down_sync(0xffffffffu, s, o);
    if (lane == 0) g_cnorm_arr[warp] = s;
}

// ================== pass 1: hh GEMM + argmin + candidate dump ==============
__device__ __forceinline__ void issue_loads(int vc, int stage, uint32_t smbase,
                                            int row0, int col0, int tid) {
    const int kof = vc * KC;
    const uint32_t sa = smbase + stage * STAGE_BYTES;
    const uint32_t sb = sa + TILE_BYTES;
    #pragma unroll
    for (int j = 0; j < 4; j++) {
        int o = tid + j * 256, r = o >> 3, seg = o & 7;
        uint32_t sw = sw128((uint32_t)(r * 128 + seg * 16));
        CP_ASYNC16(sa + sw, g_Xh + (size_t)(row0 + r) * DIM + kof + seg * 8);
        CP_ASYNC16(sb + sw, g_Ch + (size_t)(col0 + r) * DIM + kof + seg * 8);
    }
}

__global__ void __launch_bounds__(256, 2)
gemm_argmin_mma(void) {
    extern __shared__ char smem[];
    const uint32_t smbase = smem_u32(smem);
    const int tid  = threadIdx.x;
    const int wid  = tid >> 5;
    const int lane = tid & 31;
    const int warp_m = wid >> 2;
    const int warp_n = wid & 3;
    const int row0 = blockIdx.y * BM;
    const int col0 = blockIdx.x * BN;

    float acc[4][4][4];
    #pragma unroll
    for (int a = 0; a < 4; a++)
        #pragma unroll
        for (int b = 0; b < 4; b++)
            #pragma unroll
            for (int c = 0; c < 4; c++) acc[a][b][c] = 0.f;

    const int a_row = warp_m * 64 + (lane & 7) + 8 * ((lane >> 3) & 1);
    const int a_cb0 = (lane >> 4) * 16;
    const int b_row = warp_n * 32 + (lane & 7) + 8 * (lane >> 4);
    const int b_cb0 = ((lane >> 3) & 1) * 16;

    issue_loads(0, 0, smbase, row0, col0, tid);
    CP_COMMIT();
    issue_loads(1, 1, smbase, row0, col0, tid);
    CP_COMMIT();

    #pragma unroll 1
    for (int vc = 0; vc < NVC; vc++) {
        if (vc < NVC - 1) asm volatile("cp.async.wait_group 1;" ::: "memory");
        else              asm volatile("cp.async.wait_group 0;" ::: "memory");
        __syncthreads();
        if (vc + 2 < NVC) {
            issue_loads(vc + 2, (vc + 2) % NSTAGE, smbase, row0, col0, tid);
            CP_COMMIT();
        }
        const uint32_t sa = smbase + (vc % NSTAGE) * STAGE_BYTES;
        const uint32_t sb = sa + TILE_BYTES;
        #pragma unroll
        for (int ks = 0; ks < KC / 16; ks++) {
            uint32_t afr[4][4], bfr[2][4];
            #pragma unroll
            for (int mi = 0; mi < 4; mi++) {
                uint32_t off = (uint32_t)((a_row + mi * 16) * 128 + ks * 32 + a_cb0);
                ldmatrix_x4(afr[mi], sa + sw128(off));
            }
            #pragma unroll
            for (int nj = 0; nj < 2; nj++) {
                uint32_t off = (uint32_t)((b_row + nj * 16) * 128 + ks * 32 + b_cb0);
                ldmatrix_x4(bfr[nj], sb + sw128(off));
            }
            #pragma unroll
            for (int mi = 0; mi < 4; mi++)
                #pragma unroll
                for (int ni = 0; ni < 4; ni++) {
                    const uint32_t* bf = bfr[ni >> 1];
                    uint32_t b0 = (ni & 1) ? bf[2] : bf[0];
                    uint32_t b1 = (ni & 1) ? bf[3] : bf[1];
                    mma_16816(acc[mi][ni], afr[mi], b0, b1);
                }
        }
        // stage (vc+2)%3 written next iter was last read at vc-1; the barrier
        // at the top of iteration vc+1 orders the reuse.
    }

    // ---- epilogue: approx argmin + live-threshold candidate dump ----
    float cn[4][2];
    #pragma unroll
    for (int ni = 0; ni < 4; ni++) {
        int col = col0 + warp_n * 32 + ni * 8 + (lane & 3) * 2;
        cn[ni][0] = __ldg(&g_cnorm_arr[col]);
        cn[ni][1] = __ldg(&g_cnorm_arr[col + 1]);
    }
    #pragma unroll
    for (int mi = 0; mi < 4; mi++) {
        #pragma unroll
        for (int rp = 0; rp < 2; rp++) {
            const int row = row0 + warp_m * 64 + mi * 16 + (lane >> 2) + 8 * rp;
            float best_d = FLT_MAX;
            int   best_c = 0;
            #pragma unroll
            for (int ni = 0; ni < 4; ni++)
                #pragma unroll
                for (int c = 0; c < 2; c++) {
                    int col = col0 + warp_n * 32 + ni * 8 + (lane & 3) * 2 + c;
                    float d = cn[ni][c] - 2.0f * acc[mi][ni][rp * 2 + c];
                    if (d < best_d) { best_d = d; best_c = col; }
                }
            unsigned long long p =
                ((unsigned long long)float_to_ordered(best_d) << 32) | (unsigned)best_c;
            float qd = best_d;
            #pragma unroll
            for (int m = 1; m < 4; m <<= 1) {
                unsigned long long q = __shfl_xor_sync(0xffffffffu, p, m);
                if (q < p) p = q;
                qd = fminf(qd, __shfl_xor_sync(0xffffffffu, qd, m));
            }
            if ((lane & 3) == 0) atomicMin(&g_best[row], p);
            unsigned long long gb = *((volatile unsigned long long*)&g_best[row]);
            float gl = ordered_to_float((unsigned)(gb >> 32));
            const float thr = fminf(qd, gl) + __ldg(&g_margin[row]);
            #pragma unroll
            for (int ni = 0; ni < 4; ni++)
                #pragma unroll
                for (int c = 0; c < 2; c++) {
                    int col = col0 + warp_n * 32 + ni * 8 + (lane & 3) * 2 + c;
                    float d = cn[ni][c] - 2.0f * acc[mi][ni][rp * 2 + c];
                    if (d <= thr) {
                        unsigned slot = atomicAdd(&g_candcnt[row], 1u);
                        if (slot < CAP)
                            g_cand[(size_t)row * CAP + slot] = (unsigned)col;
                    }
                }
        }
    }
}

// ========== pass 2: exact fp64 refinement + fused gather ===================
__device__ __forceinline__ double warp_exact_dist(const float* __restrict__ X,
                                                  const float* __restrict__ C,
                                                  int row, int col, int lane) {
    const float* xr = X + (size_t)row * DIM;
    const float* cr = C + (size_t)col * DIM;
    double dot = 0.0, cn = 0.0;
    for (int j = lane; j < DIM; j += 32) {
        double cv = (double)cr[j];
        dot += (double)xr[j] * cv;
        cn  += cv * cv;
    }
    #pragma unroll
    for (int o = 16; o > 0; o >>= 1) {
        dot += __shfl_down_sync(0xffffffffu, dot, o);
        cn  += __shfl_down_sync(0xffffffffu, cn,  o);
    }
    return cn - 2.0 * dot;   // valid on lane 0
}

__global__ void refine_gather_kernel(const float* __restrict__ X,
                                     const float* __restrict__ C,
                                     float* __restrict__ out) {
    const int warp = (blockIdx.x * blockDim.x + threadIdx.x) >> 5;
    const int lane = threadIdx.x & 31;
    if (warp >= N_ROWS) return;
    const int row = warp;

    const unsigned cnt_raw = g_candcnt[row];
    double best_d = DBL_MAX;
    int    best_c = 0x7FFFFFFF;

    if (cnt_raw > CAP) {
        for (int col = 0; col < K_CODES; col++) {
            double d = warp_exact_dist(X, C, row, col, lane);
            if (lane == 0 && d < best_d) { best_d = d; best_c = col; }
        }
    } else {
        const int cnt = (int)cnt_raw;
        for (int i = 0; i < cnt; i++) {
            int c = (int)g_cand[(size_t)row * CAP + i];
            double d = warp_exact_dist(X, C, row, c, lane);
            if (lane == 0 && (d < best_d || (d == best_d && c < best_c))) {
                best_d = d; best_c = c;
            }
        }
    }
    best_c = __shfl_sync(0xffffffffu, best_c, 0);

    // fused gather: out0 = q; out1 = x + (q - x) with fp32 rounding
    const float4* src = (const float4*)(C + (size_t)best_c * DIM);
    const float4* xs  = (const float4*)(X + (size_t)row * DIM);
    float4* d0 = (float4*)(out + (size_t)row * DIM);
    float4* d1 = (float4*)(out + ((size_t)N_ROWS + row) * DIM);
    #pragma unroll
    for (int t = 0; t < 4; t++) {
        int i = lane + 32 * t;
        float4 q = src[i];
        float4 x = xs[i];
        d0[i] = q;
        float4 st;
        st.x = x.x + (q.x - x.x);
        st.y = x.y + (q.y - x.y);
        st.z = x.z + (q.z - x.z);
        st.w = x.w + (q.w - x.w);
        d1[i] = st;
    }
}

// ===========================================================================
extern "C" void kernel_launch(void* const* d_in, const int* in_sizes, int n_in,
                              void* d_out, int out_size) {
    const float* x  = (const float*)d_in[0];
    const float* cb = (const float*)d_in[1];
    float* out = (float*)d_out;
    (void)in_sizes; (void)n_in; (void)out_size;

    cudaFuncSetAttribute(gemm_argmin_mma,
                         cudaFuncAttributeMaxDynamicSharedMemorySize, SMEM_TOTAL);

    prep_x_kernel<<<(N_ROWS * 32 + 255) / 256, 256>>>(x);
    prep_c_kernel<<<(K_CODES * 32 + 255) / 256, 256>>>(cb);

    dim3 grid(K_CODES / BN, N_ROWS / BM);   // (64, 256)
    gemm_argmin_mma<<<grid, 256, SMEM_TOTAL>>>();

    refine_gather_kernel<<<(N_ROWS * 32 + 255) / 256, 256>>>(x, cb, out);
}